// round 11
// baseline (speedup 1.0000x reference)
#include <cuda_runtime.h>
#include <cuda_fp16.h>
#include <math.h>
#include <stdint.h>

// Problem constants
#define BSZ       256
#define NNK       255
#define DIM       128
#define SIGMA_C   0.07f
#define REG_C     0.1f
#define ETA_C     0.001f
#define NITERS    1000

// ---------------- device globals (scratch; no allocations allowed) ----------
__device__ __align__(16) float g_ftr[2 * BSZ * DIM];   // 512 x 128 normalized features
__device__ __align__(16) float g_K[BSZ * 2 * BSZ];     // 256 x 512 fp32 kernel matrix
__device__ __align__(16) float g_partial[BSZ * 8];     // per-batch stats partials

// ---------------- P1: feature normalization --------------------------------
__global__ void norm_kernel(const float* __restrict__ z) {
    int b = blockIdx.x;
    int d = threadIdx.x;
    float z0 = z[(b * 2 + 0) * DIM + d];
    float z1 = z[(b * 2 + 1) * DIM + d];
    float n = fmaxf(sqrtf(z0 * z0 + z1 * z1), 1e-12f);
    g_ftr[b * DIM + d]         = z0 / n;
    g_ftr[(BSZ + b) * DIM + d] = z1 / n;
}

// ---------------- P2: RBF kernel matrix K (256 x 512) ----------------------
__global__ void rbf_kernel_mat() {
    __shared__ float fi[DIM];
    int i = blockIdx.x;
    if (threadIdx.x < DIM) fi[threadIdx.x] = g_ftr[i * DIM + threadIdx.x];
    __syncthreads();
    for (int j = threadIdx.x; j < 2 * BSZ; j += blockDim.x) {
        const float* fj = &g_ftr[j * DIM];
        float d = 0.0f;
        #pragma unroll 8
        for (int c = 0; c < DIM; ++c) {
            float df = fi[c] - fj[c];
            d = fmaf(df, df, d);
        }
        g_K[i * (2 * BSZ) + j] = expf(-SIGMA_C * d);
    }
}

// ---------------- MMA / LDSM helpers ----------------------------------------
__device__ __forceinline__ void mma16816(float* d, const uint32_t* a,
                                         uint32_t b0, uint32_t b1) {
    asm volatile(
        "mma.sync.aligned.m16n8k16.row.col.f32.f16.f16.f32 "
        "{%0,%1,%2,%3}, {%4,%5,%6,%7}, {%8,%9}, {%0,%1,%2,%3};"
        : "+f"(d[0]), "+f"(d[1]), "+f"(d[2]), "+f"(d[3])
        : "r"(a[0]), "r"(a[1]), "r"(a[2]), "r"(a[3]), "r"(b0), "r"(b1));
}

__device__ __forceinline__ void ldsm4t(uint32_t& r0, uint32_t& r1,
                                       uint32_t& r2, uint32_t& r3, uint32_t addr) {
    asm volatile("ldmatrix.sync.aligned.m8n8.x4.trans.shared.b16 {%0,%1,%2,%3}, [%4];"
                 : "=r"(r0), "=r"(r1), "=r"(r2), "=r"(r3) : "r"(addr));
}

__device__ __forceinline__ uint32_t packh2(float lo, float hi) {
    __half2 h = __floats2half2_rn(lo, hi);
    return *(uint32_t*)&h;
}

__device__ __forceinline__ float blkred(float v, volatile float* scr, int tid) {
    scr[tid] = v;
    __syncthreads();
    #pragma unroll
    for (int s = 128; s > 0; s >>= 1) {
        if (tid < s) scr[tid] = scr[tid] + scr[tid + s];
        __syncthreads();
    }
    float r = scr[0];
    __syncthreads();
    return r;
}

// ---------------- P3: persistent dual-pipe PGD kernel -----------------------
// 128 CTAs x 512 threads (16 warps); CTA c owns batches (2c, 2c+1).
// Matvec G = KK0 @ Y split across pipes by k:
//   warps 0-7  (tensor): k in [0,128), rows [64w, 64w+64), HMMA f32-acc.
//   warps 8-15 (fma)   : k in [128,256), row = 32*(w-8)+lane, E in 64 half2
//                        registers, HFMA2 fp16 accumulation.
// Scalar phase: thread t owns (batch t>>8, slot t&255). 3 plain barriers (R5).
__global__ void __launch_bounds__(512, 1)
pgd_kernel(const float* __restrict__ alpha_init) {
    __shared__ __align__(16) __half Bmat[256 * 8];   // ldsm layout; cols 0,1 live
    __shared__ __align__(16) __half ysB[2 * 256];    // [h][slot], k-contiguous
    __shared__ float Gp[2 * 256];                    // tensor partial [batch][row]
    __shared__ float GpF[2 * 256];                   // fma partial    [batch][row]
    __shared__ __align__(32) float SaPart[16];
    __shared__ __align__(32) float NPart[16];
    __shared__ float Wst[16][6];                     // tail stats partials

    const int tid  = threadIdx.x;
    const int wid  = tid >> 5;
    const int lane = tid & 31;
    const int gid  = lane >> 2;
    const int tig  = lane & 3;
    const int h    = tid >> 8;        // batch half (0/1)
    const int s    = tid & 255;       // slot
    const int b0   = blockIdx.x * 2;
    const int bh   = b0 + h;
    const bool isTensor = (wid < 8);

    // ---- prologue: per-role operand staging ----
    uint32_t afr[2][8][4];            // tensor warps: A frags, k-tiles 0..7
    __half2  ep[64];                  // fma warps: E row slice, k in [128,256)
    int rF = 0;
    if (isTensor) {
        const int Rw = 32 * wid;
        #pragma unroll
        for (int m = 0; m < 2; ++m) {
            const int r0 = Rw + 16 * m + gid;
            const int r1 = r0 + 8;
            #pragma unroll
            for (int kt = 0; kt < 8; ++kt) {
                const int c = kt * 16 + 2 * tig;
                float v00 = (r0 == c)     ? 0.f : g_K[r0 * 512 + c];
                float v01 = (r0 == c + 1) ? 0.f : g_K[r0 * 512 + c + 1];
                float v10 = (r1 == c)     ? 0.f : g_K[r1 * 512 + c];
                float v11 = (r1 == c + 1) ? 0.f : g_K[r1 * 512 + c + 1];
                float w00 = (r0 == c + 8) ? 0.f : g_K[r0 * 512 + c + 8];
                float w01 = (r0 == c + 9) ? 0.f : g_K[r0 * 512 + c + 9];
                float w10 = (r1 == c + 8) ? 0.f : g_K[r1 * 512 + c + 8];
                float w11 = (r1 == c + 9) ? 0.f : g_K[r1 * 512 + c + 9];
                afr[m][kt][0] = packh2(v00, v01);
                afr[m][kt][1] = packh2(v10, v11);
                afr[m][kt][2] = packh2(w00, w01);
                afr[m][kt][3] = packh2(w10, w11);
            }
        }
    } else {
        rF = 32 * (wid - 8) + lane;
        #pragma unroll
        for (int j = 0; j < 64; ++j) {
            const int k0 = 128 + 2 * j;
            float e0 = (k0 == rF)     ? 0.f : g_K[rF * 512 + k0];
            float e1 = (k0 + 1 == rF) ? 0.f : g_K[rF * 512 + k0 + 1];
            uint32_t p = packh2(e0, e1);
            ep[j] = *(__half2*)&p;
        }
    }

    // zero Bmat (cols 2..7 stay zero forever)
    ((uint32_t*)Bmat)[tid]       = 0u;
    ((uint32_t*)Bmat)[tid + 512] = 0u;

    // per-thread constants / state
    const float rK  = g_K[bh * 512 + s];
    const bool  vld = (s != bh);
    float a = 0.f, ap = 0.f;
    if (vld) {
        int i = s - (s > bh);
        a = fminf(fmaxf(alpha_init[bh * NNK + i], 0.f), 1.f);
        ap = a;
    }

    // prologue Sigma(a) warp partials (consumed post-bar1 of it=0)
    {
        float t = a;
        #pragma unroll
        for (int off = 16; off; off >>= 1) t += __shfl_xor_sync(0xffffffffu, t, off);
        if (lane == 0) SaPart[wid] = t;
    }
    float Sa = 0.f;   // junk until first sum; beta(0)=0 makes Sap irrelevant at it=0

    const uint32_t baddr =
        (uint32_t)__cvta_generic_to_shared(Bmat) + (uint32_t)lane * 16u;

    __syncthreads();

    for (int it = 0; it < NITERS; ++it) {
        float tf   = (float)it;
        float beta = __fdividef(tf, tf + 3.0f);
        float y    = vld ? fmaf(beta, a - ap, a) : 0.f;
        __half yh  = __float2half(y);
        Bmat[s * 8 + h]  = yh;
        ysB[h * 256 + s] = yh;
        __syncthreads();                                      // bar 1

        // running-scalar S (partials published before bar1)
        float Sap = Sa;
        {
            float4 p0 = *(const float4*)&SaPart[h * 8];
            float4 p1 = *(const float4*)&SaPart[h * 8 + 4];
            Sa = ((p0.x + p0.y) + (p0.z + p0.w)) + ((p1.x + p1.y) + (p1.z + p1.w));
        }
        float S = fmaf(beta, Sa - Sap, Sa);

        if (isTensor) {
            // ---- tensor half: k in [0,128), rows [32w, 32w+32) ----
            float dm0[4] = {0, 0, 0, 0}, dm1[4] = {0, 0, 0, 0};
            #pragma unroll
            for (int c2 = 0; c2 < 4; ++c2) {
                uint32_t q0, q1, q2, q3;
                ldsm4t(q0, q1, q2, q3, baddr + (uint32_t)c2 * 512u);
                mma16816(dm0, afr[0][2 * c2],     q0, q1);
                mma16816(dm1, afr[1][2 * c2],     q0, q1);
                mma16816(dm0, afr[0][2 * c2 + 1], q2, q3);
                mma16816(dm1, afr[1][2 * c2 + 1], q2, q3);
            }
            if (tig == 0) {
                int ra = 32 * wid + gid;
                Gp[ra]            = dm0[0];   // batch0
                Gp[256 + ra]      = dm0[1];   // batch1
                Gp[ra + 8]        = dm0[2];
                Gp[256 + ra + 8]  = dm0[3];
                int rb = ra + 16;
                Gp[rb]            = dm1[0];
                Gp[256 + rb]      = dm1[1];
                Gp[rb + 8]        = dm1[2];
                Gp[256 + rb + 8]  = dm1[3];
            }
        } else {
            // ---- fma half: k in [128,256), row rF, E in registers ----
            __half2 a00 = __floats2half2_rn(0.f, 0.f), a01 = a00;
            __half2 a10 = a00, a11 = a00;
            const char* yb0 = (const char*)ysB + 256;   // h=0, k=128..
            const char* yb1 = (const char*)ysB + 768;   // h=1, k=128..
            #pragma unroll 8
            for (int j2 = 0; j2 < 32; ++j2) {
                uint2 w0 = *(const uint2*)(yb0 + 8 * j2);
                uint2 w1 = *(const uint2*)(yb1 + 8 * j2);
                a00 = __hfma2(ep[2 * j2],     *(__half2*)&w0.x, a00);
                a01 = __hfma2(ep[2 * j2 + 1], *(__half2*)&w0.y, a01);
                a10 = __hfma2(ep[2 * j2],     *(__half2*)&w1.x, a10);
                a11 = __hfma2(ep[2 * j2 + 1], *(__half2*)&w1.y, a11);
            }
            float gf0 = (__low2float(a00) + __high2float(a00))
                      + (__low2float(a01) + __high2float(a01));
            float gf1 = (__low2float(a10) + __high2float(a10))
                      + (__low2float(a11) + __high2float(a11));
            GpF[rF]       = gf0;   // batch0
            GpF[256 + rF] = gf1;   // batch1
        }
        __syncthreads();                                      // bar 2

        float G  = Gp[h * 256 + s]  + GpF[h * 256 + s];
        float Gb = Gp[h * 256 + bh] + GpF[h * 256 + bh];
        // c = S*(1 - rowK) + 1.1*y + G - 2 ; grad = c - Gb (diag exact via +y)
        float gv = vld ? (fmaf(1.0f - rK, S, fmaf(1.1f, y, G - 2.0f)) - Gb) : 0.f;

        float nn = gv * gv;
        #pragma unroll
        for (int off = 16; off; off >>= 1)
            nn += __shfl_xor_sync(0xffffffffu, nn, off);
        if (lane == 0) NPart[wid] = nn;
        __syncthreads();                                      // bar 3

        float N;
        {
            float4 q0 = *(const float4*)&NPart[h * 8];
            float4 q1 = *(const float4*)&NPart[h * 8 + 4];
            N = ((q0.x + q0.y) + (q0.z + q0.w)) + ((q1.x + q1.y) + (q1.z + q1.w));
        }
        float inv = rsqrtf(fmaxf(N, 1e-24f));

        if (vld) {
            float an = fminf(fmaxf(fmaf(-ETA_C * inv, gv, y), 0.f), 1.f);
            ap = a; a = an;
        }

        // publish Sigma(a_new) partials for next iteration (read post-bar1)
        float t = a;
        #pragma unroll
        for (int off = 16; off; off >>= 1) t += __shfl_xor_sync(0xffffffffu, t, off);
        if (lane == 0) SaPart[wid] = t;
    }

    // ---- tail: per-batch loss/stat partials ----
    {
        float knt = g_K[s * 512 + 256 + bh];   // Ks[k=s][bh]
        float v[6];
        v[0] = vld ? a : 0.f;                  // Sigma alpha
        v[1] = vld ? a * knt : 0.f;            // Sigma alpha*KnT
        v[2] = vld ? knt : 0.f;                // Sigma KnT
        v[3] = (vld && a == 1.0f) ? 1.f : 0.f;
        v[4] = (vld && a > 0.0f) ? 1.f : 0.f;
        v[5] = (vld && a == 0.0f) ? 1.f : 0.f;
        #pragma unroll
        for (int j = 0; j < 6; ++j) {
            float t = v[j];
            #pragma unroll
            for (int off = 16; off; off >>= 1)
                t += __shfl_xor_sync(0xffffffffu, t, off);
            if (lane == 0) Wst[wid][j] = t;
        }
        __syncthreads();
        if (lane == 0 && (wid == 0 || wid == 8)) {
            int wb = (wid == 0) ? 0 : 8;
            int bb = b0 + (wid >> 3);
            float sum[6] = {0, 0, 0, 0, 0, 0};
            #pragma unroll
            for (int w = 0; w < 8; ++w)
                #pragma unroll
                for (int j = 0; j < 6; ++j) sum[j] += Wst[wb + w][j];
            float pos = g_K[bb * 512 + 256 + bb];
            float* P = &g_partial[bb * 8];
            P[0] = sum[0] * pos;   // alpha_x * pos
            P[1] = sum[1];         // Sigma alpha*KnT
            P[2] = pos;
            P[3] = sum[2];
            P[4] = sum[3];
            P[5] = sum[4];
            P[6] = sum[5];
        }
    }
}

// ---------------- P4: tiny finisher ----------------------------------------
__global__ void finish_kernel(float* __restrict__ out) {
    __shared__ float red[256];
    int b = threadIdx.x;
    float v0 = g_partial[b * 8 + 0];
    float v1 = g_partial[b * 8 + 1];
    float v2 = g_partial[b * 8 + 2];
    float v3 = g_partial[b * 8 + 3];
    float v4 = g_partial[b * 8 + 4];
    float v5 = g_partial[b * 8 + 5];
    float v6 = g_partial[b * 8 + 6];

    float S0 = blkred(v0, red, b);
    float S1 = blkred(v1, red, b);
    float S2 = blkred(v2, red, b);
    float S3 = blkred(v3, red, b);
    float S4 = blkred(v4, red, b);
    float S5 = blkred(v5, red, b);
    float S6 = blkred(v6, red, b);

    if (b == 0) {
        out[0] = S1 / (float)BSZ - S0 / (float)BSZ;       // neg_loss - pos_loss
        out[1] = S2 / (float)BSZ;                          // pos.mean()
        out[2] = S3 / ((float)BSZ * (float)NNK);           // KnT.mean()
        out[3] = S4 / (S5 + 1e-10f);                       // sparsity
        out[4] = S6 / ((float)BSZ * (float)NNK);           // num_zero
        out[5] = 0.0f;
    }
}

// ---------------- launch ----------------------------------------------------
extern "C" void kernel_launch(void* const* d_in, const int* in_sizes, int n_in,
                              void* d_out, int out_size) {
    const float* z  = (const float*)d_in[0];
    const float* ai = (const float*)d_in[1];
    if (n_in >= 2 && in_sizes[0] == BSZ * NNK && in_sizes[1] == BSZ * 2 * DIM) {
        const float* tmp = z; z = ai; ai = tmp;
    }

    norm_kernel<<<BSZ, DIM>>>(z);
    rbf_kernel_mat<<<BSZ, 256>>>();
    pgd_kernel<<<BSZ / 2, 512>>>(ai);
    finish_kernel<<<1, 256>>>((float*)d_out);
}

// round 12
// speedup vs baseline: 1.4015x; 1.4015x over previous
#include <cuda_runtime.h>
#include <cuda_fp16.h>
#include <math.h>
#include <stdint.h>

// Problem constants
#define BSZ       256
#define NNK       255
#define DIM       128
#define SIGMA_C   0.07f
#define REG_C     0.1f
#define ETA_C     0.001f
#define NITERS    1000

// ---------------- device globals (scratch; no allocations allowed) ----------
__device__ __align__(16) float g_ftr[2 * BSZ * DIM];   // 512 x 128 normalized features
__device__ __align__(16) float g_K[BSZ * 2 * BSZ];     // 256 x 512 fp32 kernel matrix
__device__ __align__(16) float g_partial[BSZ * 8];     // per-batch stats partials

// ---------------- P1: feature normalization --------------------------------
__global__ void norm_kernel(const float* __restrict__ z) {
    int b = blockIdx.x;
    int d = threadIdx.x;
    float z0 = z[(b * 2 + 0) * DIM + d];
    float z1 = z[(b * 2 + 1) * DIM + d];
    float n = fmaxf(sqrtf(z0 * z0 + z1 * z1), 1e-12f);
    g_ftr[b * DIM + d]         = z0 / n;
    g_ftr[(BSZ + b) * DIM + d] = z1 / n;
}

// ---------------- P2: RBF kernel matrix K (256 x 512) ----------------------
__global__ void rbf_kernel_mat() {
    __shared__ float fi[DIM];
    int i = blockIdx.x;
    if (threadIdx.x < DIM) fi[threadIdx.x] = g_ftr[i * DIM + threadIdx.x];
    __syncthreads();
    for (int j = threadIdx.x; j < 2 * BSZ; j += blockDim.x) {
        const float* fj = &g_ftr[j * DIM];
        float d = 0.0f;
        #pragma unroll 8
        for (int c = 0; c < DIM; ++c) {
            float df = fi[c] - fj[c];
            d = fmaf(df, df, d);
        }
        g_K[i * (2 * BSZ) + j] = expf(-SIGMA_C * d);
    }
}

// ---------------- MMA / LDSM / half2 helpers ---------------------------------
__device__ __forceinline__ void mma16816(float* d, const uint32_t* a,
                                         uint32_t b0, uint32_t b1) {
    asm volatile(
        "mma.sync.aligned.m16n8k16.row.col.f32.f16.f16.f32 "
        "{%0,%1,%2,%3}, {%4,%5,%6,%7}, {%8,%9}, {%0,%1,%2,%3};"
        : "+f"(d[0]), "+f"(d[1]), "+f"(d[2]), "+f"(d[3])
        : "r"(a[0]), "r"(a[1]), "r"(a[2]), "r"(a[3]), "r"(b0), "r"(b1));
}

__device__ __forceinline__ void ldsm4t(uint32_t& r0, uint32_t& r1,
                                       uint32_t& r2, uint32_t& r3, uint32_t addr) {
    asm volatile("ldmatrix.sync.aligned.m8n8.x4.trans.shared.b16 {%0,%1,%2,%3}, [%4];"
                 : "=r"(r0), "=r"(r1), "=r"(r2), "=r"(r3) : "r"(addr));
}

// hfma2 on raw b32 registers (no pointer reinterpretation of reg arrays)
__device__ __forceinline__ uint32_t hfma2b(uint32_t a, uint32_t b, uint32_t c) {
    uint32_t d;
    asm("fma.rn.f16x2 %0, %1, %2, %3;" : "=r"(d) : "r"(a), "r"(b), "r"(c));
    return d;
}

__device__ __forceinline__ float2 h2f2(uint32_t h) {
    __half2 v = *(__half2*)&h;
    return __half22float2(v);
}

__device__ __forceinline__ uint32_t packh2(float lo, float hi) {
    __half2 h = __floats2half2_rn(lo, hi);
    return *(uint32_t*)&h;
}

__device__ __forceinline__ float blkred(float v, volatile float* scr, int tid) {
    scr[tid] = v;
    __syncthreads();
    #pragma unroll
    for (int s = 128; s > 0; s >>= 1) {
        if (tid < s) scr[tid] = scr[tid] + scr[tid + s];
        __syncthreads();
    }
    float r = scr[0];
    __syncthreads();
    return r;
}

// ---------------- P3: persistent dual-pipe PGD kernel -----------------------
// 128 CTAs x 512 threads (16 warps); CTA c owns batches (2c, 2c+1).
// Matvec G = KK0 @ Y split across pipes by k:
//   warps 0-7  (tensor): k in [0,128), rows [32w, 32w+32), HMMA f32-acc.
//   warps 8-15 (fma)   : k in [128,256), row 32*(w-8)+lane, HFMA2 with
//                        chunked fp32 combine (32-k chunks).
// Operand registers UNIONED in ubuf[64] (A-frags / E-row half2s) -> no spills.
__global__ void __launch_bounds__(512, 1)
pgd_kernel(const float* __restrict__ alpha_init) {
    __shared__ __align__(16) __half Bmat[256 * 8];   // ldsm staging, slots 0..127 used
    __shared__ __align__(16) __half ysB[2 * 128];    // [h][slot-128] fma staging
    __shared__ float Gp[2 * 256];                    // tensor partial [batch][row]
    __shared__ float GpF[2 * 256];                   // fma partial    [batch][row]
    __shared__ __align__(32) float SaPart[16];
    __shared__ __align__(32) float NPart[16];
    __shared__ float Wst[16][6];                     // tail stats partials

    const int tid  = threadIdx.x;
    const int wid  = tid >> 5;
    const int lane = tid & 31;
    const int gid  = lane >> 2;
    const int tig  = lane & 3;
    const int h    = tid >> 8;        // batch half (0/1)
    const int s    = tid & 255;       // slot
    const int b0   = blockIdx.x * 2;
    const int bh   = b0 + h;
    const bool isTensor = (wid < 8);

    // ---- prologue: UNION operand buffer ----
    // tensor warps: ubuf[m*32 + kt*4 + j] = A-frag (m-tile m, k-tile kt)
    // fma warps   : ubuf[j] = E[rF][128+2j .. 128+2j+1] as half2
    uint32_t ubuf[64];
    int rF = 0;
    if (isTensor) {
        const int Rw = 32 * wid;
        #pragma unroll
        for (int m = 0; m < 2; ++m) {
            const int r0 = Rw + 16 * m + gid;
            const int r1 = r0 + 8;
            #pragma unroll
            for (int kt = 0; kt < 8; ++kt) {
                const int c = kt * 16 + 2 * tig;
                float v00 = (r0 == c)     ? 0.f : g_K[r0 * 512 + c];
                float v01 = (r0 == c + 1) ? 0.f : g_K[r0 * 512 + c + 1];
                float v10 = (r1 == c)     ? 0.f : g_K[r1 * 512 + c];
                float v11 = (r1 == c + 1) ? 0.f : g_K[r1 * 512 + c + 1];
                float w00 = (r0 == c + 8) ? 0.f : g_K[r0 * 512 + c + 8];
                float w01 = (r0 == c + 9) ? 0.f : g_K[r0 * 512 + c + 9];
                float w10 = (r1 == c + 8) ? 0.f : g_K[r1 * 512 + c + 8];
                float w11 = (r1 == c + 9) ? 0.f : g_K[r1 * 512 + c + 9];
                ubuf[m * 32 + kt * 4 + 0] = packh2(v00, v01);
                ubuf[m * 32 + kt * 4 + 1] = packh2(v10, v11);
                ubuf[m * 32 + kt * 4 + 2] = packh2(w00, w01);
                ubuf[m * 32 + kt * 4 + 3] = packh2(w10, w11);
            }
        }
    } else {
        rF = 32 * (wid - 8) + lane;
        #pragma unroll
        for (int j = 0; j < 64; ++j) {
            const int k0 = 128 + 2 * j;
            float e0 = (k0 == rF)     ? 0.f : g_K[rF * 512 + k0];
            float e1 = (k0 + 1 == rF) ? 0.f : g_K[rF * 512 + k0 + 1];
            ubuf[j] = packh2(e0, e1);
        }
    }

    // zero Bmat (cols 2..7 stay zero forever)
    ((uint32_t*)Bmat)[tid]       = 0u;
    ((uint32_t*)Bmat)[tid + 512] = 0u;

    // per-thread constants / state
    const float rK  = g_K[bh * 512 + s];
    const bool  vld = (s != bh);
    float a = 0.f, ap = 0.f;
    if (vld) {
        int i = s - (s > bh);
        a = fminf(fmaxf(alpha_init[bh * NNK + i], 0.f), 1.f);
        ap = a;
    }

    // prologue Sigma(a) warp partials (consumed post-bar1 of it=0)
    {
        float t = a;
        #pragma unroll
        for (int off = 16; off; off >>= 1) t += __shfl_xor_sync(0xffffffffu, t, off);
        if (lane == 0) SaPart[wid] = t;
    }
    float Sa = 0.f;   // junk until first sum; beta(0)=0 makes Sap irrelevant at it=0

    const uint32_t baddr =
        (uint32_t)__cvta_generic_to_shared(Bmat) + (uint32_t)lane * 16u;
    const bool lowSlot = (s < 128);

    __syncthreads();

    for (int it = 0; it < NITERS; ++it) {
        float tf   = (float)it;
        float beta = __fdividef(tf, tf + 3.0f);
        float y    = vld ? fmaf(beta, a - ap, a) : 0.f;
        __half yh  = __float2half(y);
        if (lowSlot) Bmat[s * 8 + h] = yh;         // tensor half reads slots 0..127
        else         ysB[h * 128 + (s - 128)] = yh; // fma half reads slots 128..255
        __syncthreads();                                      // bar 1

        // running-scalar S (partials published before bar1)
        float Sap = Sa;
        {
            float4 p0 = *(const float4*)&SaPart[h * 8];
            float4 p1 = *(const float4*)&SaPart[h * 8 + 4];
            Sa = ((p0.x + p0.y) + (p0.z + p0.w)) + ((p1.x + p1.y) + (p1.z + p1.w));
        }
        float S = fmaf(beta, Sa - Sap, Sa);

        if (isTensor) {
            // ---- tensor half: k in [0,128), rows [32w, 32w+32) ----
            float dm0[4] = {0, 0, 0, 0}, dm1[4] = {0, 0, 0, 0};
            #pragma unroll
            for (int c2 = 0; c2 < 4; ++c2) {
                uint32_t q0, q1, q2, q3;
                ldsm4t(q0, q1, q2, q3, baddr + (uint32_t)c2 * 512u);
                mma16816(dm0, &ubuf[(2 * c2) * 4],            q0, q1);
                mma16816(dm1, &ubuf[32 + (2 * c2) * 4],       q0, q1);
                mma16816(dm0, &ubuf[(2 * c2 + 1) * 4],        q2, q3);
                mma16816(dm1, &ubuf[32 + (2 * c2 + 1) * 4],   q2, q3);
            }
            if (tig == 0) {
                int ra = 32 * wid + gid;
                Gp[ra]            = dm0[0];   // batch0
                Gp[256 + ra]      = dm0[1];   // batch1
                Gp[ra + 8]        = dm0[2];
                Gp[256 + ra + 8]  = dm0[3];
                int rb = ra + 16;
                Gp[rb]            = dm1[0];
                Gp[256 + rb]      = dm1[1];
                Gp[rb + 8]        = dm1[2];
                Gp[256 + rb + 8]  = dm1[3];
            }
        } else {
            // ---- fma half: k in [128,256), row rF, chunked fp32 combine ----
            float gf0 = 0.f, gf1 = 0.f;
            #pragma unroll
            for (int c = 0; c < 4; ++c) {
                const uint4* y0p = (const uint4*)((const char*)ysB + c * 64);
                const uint4* y1p = (const uint4*)((const char*)ysB + 256 + c * 64);
                uint32_t p0 = 0u, q0 = 0u, p1 = 0u, q1 = 0u;
                #pragma unroll
                for (int t = 0; t < 4; ++t) {
                    uint4 w0 = y0p[t];
                    uint4 w1 = y1p[t];
                    p0 = hfma2b(ubuf[c * 16 + t * 4 + 0], w0.x, p0);
                    q0 = hfma2b(ubuf[c * 16 + t * 4 + 1], w0.y, q0);
                    p0 = hfma2b(ubuf[c * 16 + t * 4 + 2], w0.z, p0);
                    q0 = hfma2b(ubuf[c * 16 + t * 4 + 3], w0.w, q0);
                    p1 = hfma2b(ubuf[c * 16 + t * 4 + 0], w1.x, p1);
                    q1 = hfma2b(ubuf[c * 16 + t * 4 + 1], w1.y, q1);
                    p1 = hfma2b(ubuf[c * 16 + t * 4 + 2], w1.z, p1);
                    q1 = hfma2b(ubuf[c * 16 + t * 4 + 3], w1.w, q1);
                }
                float2 f0p = h2f2(p0), f0q = h2f2(q0);
                float2 f1p = h2f2(p1), f1q = h2f2(q1);
                gf0 += (f0p.x + f0p.y) + (f0q.x + f0q.y);
                gf1 += (f1p.x + f1p.y) + (f1q.x + f1q.y);
            }
            GpF[rF]       = gf0;   // batch0
            GpF[256 + rF] = gf1;   // batch1
        }
        __syncthreads();                                      // bar 2

        float G  = Gp[h * 256 + s]  + GpF[h * 256 + s];
        float Gb = Gp[h * 256 + bh] + GpF[h * 256 + bh];
        // c = S*(1 - rowK) + 1.1*y + G - 2 ; grad = c - Gb (diag exact via +y)
        float gv = vld ? (fmaf(1.0f - rK, S, fmaf(1.1f, y, G - 2.0f)) - Gb) : 0.f;

        float nn = gv * gv;
        #pragma unroll
        for (int off = 16; off; off >>= 1)
            nn += __shfl_xor_sync(0xffffffffu, nn, off);
        if (lane == 0) NPart[wid] = nn;
        __syncthreads();                                      // bar 3

        float N;
        {
            float4 q0 = *(const float4*)&NPart[h * 8];
            float4 q1 = *(const float4*)&NPart[h * 8 + 4];
            N = ((q0.x + q0.y) + (q0.z + q0.w)) + ((q1.x + q1.y) + (q1.z + q1.w));
        }
        float inv = rsqrtf(fmaxf(N, 1e-24f));

        if (vld) {
            float an = fminf(fmaxf(fmaf(-ETA_C * inv, gv, y), 0.f), 1.f);
            ap = a; a = an;
        }

        // publish Sigma(a_new) partials for next iteration (read post-bar1)
        float t = a;
        #pragma unroll
        for (int off = 16; off; off >>= 1) t += __shfl_xor_sync(0xffffffffu, t, off);
        if (lane == 0) SaPart[wid] = t;
    }

    // ---- tail: per-batch loss/stat partials ----
    {
        float knt = g_K[s * 512 + 256 + bh];   // Ks[k=s][bh]
        float v[6];
        v[0] = vld ? a : 0.f;                  // Sigma alpha
        v[1] = vld ? a * knt : 0.f;            // Sigma alpha*KnT
        v[2] = vld ? knt : 0.f;                // Sigma KnT
        v[3] = (vld && a == 1.0f) ? 1.f : 0.f;
        v[4] = (vld && a > 0.0f) ? 1.f : 0.f;
        v[5] = (vld && a == 0.0f) ? 1.f : 0.f;
        #pragma unroll
        for (int j = 0; j < 6; ++j) {
            float t = v[j];
            #pragma unroll
            for (int off = 16; off; off >>= 1)
                t += __shfl_xor_sync(0xffffffffu, t, off);
            if (lane == 0) Wst[wid][j] = t;
        }
        __syncthreads();
        if (lane == 0 && (wid == 0 || wid == 8)) {
            int wb = (wid == 0) ? 0 : 8;
            int bb = b0 + (wid >> 3);
            float sum[6] = {0, 0, 0, 0, 0, 0};
            #pragma unroll
            for (int w = 0; w < 8; ++w)
                #pragma unroll
                for (int j = 0; j < 6; ++j) sum[j] += Wst[wb + w][j];
            float pos = g_K[bb * 512 + 256 + bb];
            float* P = &g_partial[bb * 8];
            P[0] = sum[0] * pos;   // alpha_x * pos
            P[1] = sum[1];         // Sigma alpha*KnT
            P[2] = pos;
            P[3] = sum[2];
            P[4] = sum[3];
            P[5] = sum[4];
            P[6] = sum[5];
        }
    }
}

// ---------------- P4: tiny finisher ----------------------------------------
__global__ void finish_kernel(float* __restrict__ out) {
    __shared__ float red[256];
    int b = threadIdx.x;
    float v0 = g_partial[b * 8 + 0];
    float v1 = g_partial[b * 8 + 1];
    float v2 = g_partial[b * 8 + 2];
    float v3 = g_partial[b * 8 + 3];
    float v4 = g_partial[b * 8 + 4];
    float v5 = g_partial[b * 8 + 5];
    float v6 = g_partial[b * 8 + 6];

    float S0 = blkred(v0, red, b);
    float S1 = blkred(v1, red, b);
    float S2 = blkred(v2, red, b);
    float S3 = blkred(v3, red, b);
    float S4 = blkred(v4, red, b);
    float S5 = blkred(v5, red, b);
    float S6 = blkred(v6, red, b);

    if (b == 0) {
        out[0] = S1 / (float)BSZ - S0 / (float)BSZ;       // neg_loss - pos_loss
        out[1] = S2 / (float)BSZ;                          // pos.mean()
        out[2] = S3 / ((float)BSZ * (float)NNK);           // KnT.mean()
        out[3] = S4 / (S5 + 1e-10f);                       // sparsity
        out[4] = S6 / ((float)BSZ * (float)NNK);           // num_zero
        out[5] = 0.0f;
    }
}

// ---------------- launch ----------------------------------------------------
extern "C" void kernel_launch(void* const* d_in, const int* in_sizes, int n_in,
                              void* d_out, int out_size) {
    const float* z  = (const float*)d_in[0];
    const float* ai = (const float*)d_in[1];
    if (n_in >= 2 && in_sizes[0] == BSZ * NNK && in_sizes[1] == BSZ * 2 * DIM) {
        const float* tmp = z; z = ai; ai = tmp;
    }

    norm_kernel<<<BSZ, DIM>>>(z);
    rbf_kernel_mat<<<BSZ, 256>>>();
    pgd_kernel<<<BSZ / 2, 512>>>(ai);
    finish_kernel<<<1, 256>>>((float*)d_out);
}

// round 13
// speedup vs baseline: 1.9013x; 1.3566x over previous
#include <cuda_runtime.h>
#include <cuda_fp16.h>
#include <math.h>
#include <stdint.h>

// Problem constants
#define BSZ       256
#define NNK       255
#define DIM       128
#define SIGMA_C   0.07f
#define REG_C     0.1f
#define ETA_C     0.001f
#define NITERS    1000

// ---------------- device globals (scratch; no allocations allowed) ----------
__device__ __align__(16) float g_ftr[2 * BSZ * DIM];   // 512 x 128 normalized features
__device__ __align__(16) float g_K[BSZ * 2 * BSZ];     // 256 x 512 fp32 kernel matrix
__device__ __align__(16) float g_partial[BSZ * 8];     // per-batch stats partials
__device__ int g_sink;                                 // dummy-kernel sink

// ---------------- P0: dummy (launch-position shim so ncu -s 5 hits pgd) -----
__global__ void dummy_kernel(int v) {
    if (threadIdx.x == 0) g_sink = v;
}

// ---------------- P1: feature normalization --------------------------------
__global__ void norm_kernel(const float* __restrict__ z) {
    int b = blockIdx.x;
    int d = threadIdx.x;
    float z0 = z[(b * 2 + 0) * DIM + d];
    float z1 = z[(b * 2 + 1) * DIM + d];
    float n = fmaxf(sqrtf(z0 * z0 + z1 * z1), 1e-12f);
    g_ftr[b * DIM + d]         = z0 / n;
    g_ftr[(BSZ + b) * DIM + d] = z1 / n;
}

// ---------------- P2: RBF kernel matrix K (256 x 512) ----------------------
__global__ void rbf_kernel_mat() {
    __shared__ float fi[DIM];
    int i = blockIdx.x;
    if (threadIdx.x < DIM) fi[threadIdx.x] = g_ftr[i * DIM + threadIdx.x];
    __syncthreads();
    for (int j = threadIdx.x; j < 2 * BSZ; j += blockDim.x) {
        const float* fj = &g_ftr[j * DIM];
        float d = 0.0f;
        #pragma unroll 8
        for (int c = 0; c < DIM; ++c) {
            float df = fi[c] - fj[c];
            d = fmaf(df, df, d);
        }
        g_K[i * (2 * BSZ) + j] = expf(-SIGMA_C * d);
    }
}

// ---------------- MMA / LDSM helpers ----------------------------------------
__device__ __forceinline__ void mma16816(float* d, const uint32_t* a,
                                         uint32_t b0, uint32_t b1) {
    asm volatile(
        "mma.sync.aligned.m16n8k16.row.col.f32.f16.f16.f32 "
        "{%0,%1,%2,%3}, {%4,%5,%6,%7}, {%8,%9}, {%0,%1,%2,%3};"
        : "+f"(d[0]), "+f"(d[1]), "+f"(d[2]), "+f"(d[3])
        : "r"(a[0]), "r"(a[1]), "r"(a[2]), "r"(a[3]), "r"(b0), "r"(b1));
}

__device__ __forceinline__ void ldsm4t(uint32_t& r0, uint32_t& r1,
                                       uint32_t& r2, uint32_t& r3, uint32_t addr) {
    asm volatile("ldmatrix.sync.aligned.m8n8.x4.trans.shared.b16 {%0,%1,%2,%3}, [%4];"
                 : "=r"(r0), "=r"(r1), "=r"(r2), "=r"(r3) : "r"(addr));
}

__device__ __forceinline__ uint32_t packh2(float lo, float hi) {
    __half2 h = __floats2half2_rn(lo, hi);
    return *(uint32_t*)&h;
}

__device__ __forceinline__ float blkred(float v, volatile float* scr, int tid) {
    scr[tid] = v;
    __syncthreads();
    #pragma unroll
    for (int s = 128; s > 0; s >>= 1) {
        if (tid < s) scr[tid] = scr[tid] + scr[tid + s];
        __syncthreads();
    }
    float r = scr[0];
    __syncthreads();
    return r;
}

// ---------------- P3: persistent HMMA-PGD kernel (R5, measured 769us) -------
// 128 CTAs x 512 threads (16 warps, 4/SMSP); CTA c owns batches (2c, 2c+1).
// Warp w owns m-tile rows [16w, 16w+16). Thread t owns (batch t>>8, slot t&255).
// KK fp16 zero-diag A-fragments in registers (64 regs/thread).
// B via ldmatrix.x4.trans from Bmat[256][8] (cols 0,1 live; 2-7 zero).
// S tracked via running scalars: S = Sa + beta*(Sa - Sap).
__global__ void __launch_bounds__(512, 1)
pgd_kernel(const float* __restrict__ alpha_init) {
    __shared__ __align__(16) __half Bmat[256 * 8];   // [slot][col] 4KB
    __shared__ float Gp[2 * 256];                    // [batch][row]
    __shared__ __align__(32) float SaPart[16];
    __shared__ __align__(32) float NPart[16];
    __shared__ float Wst[16][6];                     // tail stats partials

    const int tid  = threadIdx.x;
    const int wid  = tid >> 5;
    const int lane = tid & 31;
    const int gid  = lane >> 2;
    const int tig  = lane & 3;
    const int h    = tid >> 8;        // batch half (0/1)
    const int s    = tid & 255;       // slot
    const int b0   = blockIdx.x * 2;
    const int bh   = b0 + h;
    const int R    = wid * 16;        // this warp's m-tile row base

    // ---- prologue: A fragments (KK fp16, zero diagonal), 1 m-tile per warp
    uint32_t afr[16][4];
    {
        const int r0 = R + gid;
        const int r1 = r0 + 8;
        #pragma unroll
        for (int kt = 0; kt < 16; ++kt) {
            const int c = kt * 16 + 2 * tig;
            float v00 = (r0 == c)     ? 0.f : g_K[r0 * 512 + c];
            float v01 = (r0 == c + 1) ? 0.f : g_K[r0 * 512 + c + 1];
            float v10 = (r1 == c)     ? 0.f : g_K[r1 * 512 + c];
            float v11 = (r1 == c + 1) ? 0.f : g_K[r1 * 512 + c + 1];
            float w00 = (r0 == c + 8) ? 0.f : g_K[r0 * 512 + c + 8];
            float w01 = (r0 == c + 9) ? 0.f : g_K[r0 * 512 + c + 9];
            float w10 = (r1 == c + 8) ? 0.f : g_K[r1 * 512 + c + 8];
            float w11 = (r1 == c + 9) ? 0.f : g_K[r1 * 512 + c + 9];
            afr[kt][0] = packh2(v00, v01);
            afr[kt][1] = packh2(v10, v11);
            afr[kt][2] = packh2(w00, w01);
            afr[kt][3] = packh2(w10, w11);
        }
    }

    // zero Bmat (cols 2..7 stay zero forever)
    ((uint32_t*)Bmat)[tid]       = 0u;
    ((uint32_t*)Bmat)[tid + 512] = 0u;

    // per-thread constants / state
    const float rK  = g_K[bh * 512 + s];
    const bool  vld = (s != bh);
    float a = 0.f, ap = 0.f;
    if (vld) {
        int i = s - (s > bh);
        a = fminf(fmaxf(alpha_init[bh * NNK + i], 0.f), 1.f);
        ap = a;
    }

    // prologue Sigma(a) warp partials (consumed after first bar1)
    {
        float t = a;
        #pragma unroll
        for (int off = 16; off; off >>= 1) t += __shfl_xor_sync(0xffffffffu, t, off);
        if (lane == 0) SaPart[wid] = t;
    }
    float Sa = 0.f;   // junk until first sum; beta(0)=0 makes Sap irrelevant at it=0

    const uint32_t baddr =
        (uint32_t)__cvta_generic_to_shared(Bmat) + (uint32_t)lane * 16u;

    __syncthreads();

    for (int it = 0; it < NITERS; ++it) {
        float tf   = (float)it;
        float beta = __fdividef(tf, tf + 3.0f);
        float y    = vld ? fmaf(beta, a - ap, a) : 0.f;
        Bmat[s * 8 + h] = __float2half(y);
        __syncthreads();                                      // bar 1

        // running-scalar S (partials published before bar1)
        float Sap = Sa;
        {
            float4 p0 = *(const float4*)&SaPart[h * 8];
            float4 p1 = *(const float4*)&SaPart[h * 8 + 4];
            Sa = ((p0.x + p0.y) + (p0.z + p0.w)) + ((p1.x + p1.y) + (p1.z + p1.w));
        }
        float S = fmaf(beta, Sa - Sap, Sa);

        // ---- HMMA matvec: 8x (ldmatrix.x4.trans -> 2 MMAs), 2 acc chains ----
        float dA[4] = {0, 0, 0, 0}, dB[4] = {0, 0, 0, 0};
        #pragma unroll
        for (int c2 = 0; c2 < 8; ++c2) {
            uint32_t q0, q1, q2, q3;
            ldsm4t(q0, q1, q2, q3, baddr + (uint32_t)c2 * 512u);
            mma16816(dA, afr[2 * c2],     q0, q1);
            mma16816(dB, afr[2 * c2 + 1], q2, q3);
        }
        if (tig == 0) {
            int r = R + gid;
            Gp[r]           = dA[0] + dB[0];   // batch0, row r
            Gp[256 + r]     = dA[1] + dB[1];   // batch1, row r
            Gp[r + 8]       = dA[2] + dB[2];
            Gp[256 + r + 8] = dA[3] + dB[3];
        }
        __syncthreads();                                      // bar 2

        float G  = Gp[h * 256 + s];
        float Gb = Gp[h * 256 + bh];
        // c = S*(1 - rowK) + 1.1*y + G - 2 ; grad = c - Gb (diag exact via +y)
        float gv = vld ? (fmaf(1.0f - rK, S, fmaf(1.1f, y, G - 2.0f)) - Gb) : 0.f;

        float nn = gv * gv;
        #pragma unroll
        for (int off = 16; off; off >>= 1)
            nn += __shfl_xor_sync(0xffffffffu, nn, off);
        if (lane == 0) NPart[wid] = nn;
        __syncthreads();                                      // bar 3

        float N;
        {
            float4 q0 = *(const float4*)&NPart[h * 8];
            float4 q1 = *(const float4*)&NPart[h * 8 + 4];
            N = ((q0.x + q0.y) + (q0.z + q0.w)) + ((q1.x + q1.y) + (q1.z + q1.w));
        }
        float inv = rsqrtf(fmaxf(N, 1e-24f));

        if (vld) {
            float an = fminf(fmaxf(fmaf(-ETA_C * inv, gv, y), 0.f), 1.f);
            ap = a; a = an;
        }

        // publish Sigma(a_new) partials for next iteration (visible after bar1)
        float t = a;
        #pragma unroll
        for (int off = 16; off; off >>= 1) t += __shfl_xor_sync(0xffffffffu, t, off);
        if (lane == 0) SaPart[wid] = t;
    }

    // ---- tail: per-batch loss/stat partials ----
    {
        float knt = g_K[s * 512 + 256 + bh];   // Ks[k=s][bh]
        float v[6];
        v[0] = vld ? a : 0.f;                  // Sigma alpha
        v[1] = vld ? a * knt : 0.f;            // Sigma alpha*KnT
        v[2] = vld ? knt : 0.f;                // Sigma KnT
        v[3] = (vld && a == 1.0f) ? 1.f : 0.f;
        v[4] = (vld && a > 0.0f) ? 1.f : 0.f;
        v[5] = (vld && a == 0.0f) ? 1.f : 0.f;
        #pragma unroll
        for (int j = 0; j < 6; ++j) {
            float t = v[j];
            #pragma unroll
            for (int off = 16; off; off >>= 1)
                t += __shfl_xor_sync(0xffffffffu, t, off);
            if (lane == 0) Wst[wid][j] = t;
        }
        __syncthreads();
        if (lane == 0 && (wid == 0 || wid == 8)) {
            int wb = (wid == 0) ? 0 : 8;
            int bb = b0 + (wid >> 3);
            float sum[6] = {0, 0, 0, 0, 0, 0};
            #pragma unroll
            for (int w = 0; w < 8; ++w)
                #pragma unroll
                for (int j = 0; j < 6; ++j) sum[j] += Wst[wb + w][j];
            float pos = g_K[bb * 512 + 256 + bb];
            float* P = &g_partial[bb * 8];
            P[0] = sum[0] * pos;   // alpha_x * pos
            P[1] = sum[1];         // Sigma alpha*KnT
            P[2] = pos;
            P[3] = sum[2];
            P[4] = sum[3];
            P[5] = sum[4];
            P[6] = sum[5];
        }
    }
}

// ---------------- P4: tiny finisher ----------------------------------------
__global__ void finish_kernel(float* __restrict__ out) {
    __shared__ float red[256];
    int b = threadIdx.x;
    float v0 = g_partial[b * 8 + 0];
    float v1 = g_partial[b * 8 + 1];
    float v2 = g_partial[b * 8 + 2];
    float v3 = g_partial[b * 8 + 3];
    float v4 = g_partial[b * 8 + 4];
    float v5 = g_partial[b * 8 + 5];
    float v6 = g_partial[b * 8 + 6];

    float S0 = blkred(v0, red, b);
    float S1 = blkred(v1, red, b);
    float S2 = blkred(v2, red, b);
    float S3 = blkred(v3, red, b);
    float S4 = blkred(v4, red, b);
    float S5 = blkred(v5, red, b);
    float S6 = blkred(v6, red, b);

    if (b == 0) {
        out[0] = S1 / (float)BSZ - S0 / (float)BSZ;       // neg_loss - pos_loss
        out[1] = S2 / (float)BSZ;                          // pos.mean()
        out[2] = S3 / ((float)BSZ * (float)NNK);           // KnT.mean()
        out[3] = S4 / (S5 + 1e-10f);                       // sparsity
        out[4] = S6 / ((float)BSZ * (float)NNK);           // num_zero
        out[5] = 0.0f;
    }
}

// ---------------- launch ----------------------------------------------------
extern "C" void kernel_launch(void* const* d_in, const int* in_sizes, int n_in,
                              void* d_out, int out_size) {
    const float* z  = (const float*)d_in[0];
    const float* ai = (const float*)d_in[1];
    if (n_in >= 2 && in_sizes[0] == BSZ * NNK && in_sizes[1] == BSZ * 2 * DIM) {
        const float* tmp = z; z = ai; ai = tmp;
    }

    norm_kernel<<<BSZ, DIM>>>(z);
    rbf_kernel_mat<<<BSZ, 256>>>();
    dummy_kernel<<<1, 32>>>(0);      // shim: makes pgd the 6th process launch
    pgd_kernel<<<BSZ / 2, 512>>>(ai);
    finish_kernel<<<1, 256>>>((float*)d_out);
}